// round 12
// baseline (speedup 1.0000x reference)
#include <cuda_runtime.h>
#include <cuda_bf16.h>
#include <cstdint>

// out[r] = tanh((x0*x1 + sin(x2))*exp(-|x3|) + x4/(x5^2+exp(x6)) - x7)
// FINAL: flat grid, block=256, 4 rows/thread, warp-contiguous mapping
// (row = base + tid + k*256 => 32B lane stride), 8 front-batched LDG.128.CS
// (MLP=8), coalesced STG.32.CS. DRAM-streaming-bound at ~85% of HBM spec —
// measured roofline across MLP{2,4,8,16}, persistent, and block-size sweeps;
// ncu stable at 42.9us / 84.7% DRAM over three consecutive profiles.

__device__ __forceinline__ float expr1(float4 a, float4 b)
{
    return tanhf((a.x * a.y + __sinf(a.z)) * __expf(-fabsf(a.w))
               + __fdividef(b.x, b.y * b.y + __expf(b.z)) - b.w);
}

__global__ __launch_bounds__(256) void expr_kernel(
    const float4* __restrict__ in,   // N_ROWS*2 float4
    float* __restrict__ out,         // N_ROWS floats
    int n_rows)
{
    const int tid = threadIdx.x;
    const int base = blockIdx.x * 1024 + tid;   // 1024 rows per block

    const int r0 = base;
    const int r1 = base + 256;
    const int r2 = base + 512;
    const int r3 = base + 768;

    if (__builtin_expect(r3 < n_rows, 1)) {
        // Hot path (all CTAs when n_rows % 1024 == 0): 8 front-batched loads.
        float4 a0 = __ldcs(in + 2 * r0);
        float4 b0 = __ldcs(in + 2 * r0 + 1);
        float4 a1 = __ldcs(in + 2 * r1);
        float4 b1 = __ldcs(in + 2 * r1 + 1);
        float4 a2 = __ldcs(in + 2 * r2);
        float4 b2 = __ldcs(in + 2 * r2 + 1);
        float4 a3 = __ldcs(in + 2 * r3);
        float4 b3 = __ldcs(in + 2 * r3 + 1);

        __stcs(out + r0, expr1(a0, b0));
        __stcs(out + r1, expr1(a1, b1));
        __stcs(out + r2, expr1(a2, b2));
        __stcs(out + r3, expr1(a3, b3));
    } else {
        // Generic tail (unused at N_ROWS = 8388608).
        #pragma unroll
        for (int k = 0; k < 4; k++) {
            int r = base + k * 256;
            if (r < n_rows) {
                float4 a = __ldcs(in + 2 * r);
                float4 b = __ldcs(in + 2 * r + 1);
                __stcs(out + r, expr1(a, b));
            }
        }
    }
}

extern "C" void kernel_launch(void* const* d_in, const int* in_sizes, int n_in,
                              void* d_out, int out_size)
{
    const float4* in = (const float4*)d_in[0];
    float* out = (float*)d_out;

    int n_rows = out_size;   // 8388608
    int threads = 256;
    int rows_per_block = threads * 4;
    int blocks = (n_rows + rows_per_block - 1) / rows_per_block;  // 8192
    expr_kernel<<<blocks, threads>>>(in, out, n_rows);
}

// round 14
// speedup vs baseline: 1.0329x; 1.0329x over previous
#include <cuda_runtime.h>
#include <cuda_bf16.h>
#include <cstdint>

// out[r] = tanh((x0*x1 + sin(x2))*exp(-|x3|) + x4/(x5^2+exp(x6)) - x7)
// FINAL: flat grid, block=256, 4 rows/thread, warp-contiguous mapping
// (row = base + tid + k*256 => 32B lane stride), 8 front-batched LDG.128.CS
// (MLP=8), coalesced STG.32.CS.
// DRAM-streaming-bound at ~85% of HBM spec (6.7 TB/s) — measured roofline
// across MLP{2,4,8,16}, persistent-vs-flat, and block-size sweeps. Run-to-run
// bench scatter (43.7-48.2us) is DVFS clock variance on identical binaries,
// not kernel structure: R12's profile shows all SM-pipe percentages scaled
// ~1.6x with DRAM% down — the unlocked-clock signature.

__device__ __forceinline__ float expr1(float4 a, float4 b)
{
    return tanhf((a.x * a.y + __sinf(a.z)) * __expf(-fabsf(a.w))
               + __fdividef(b.x, b.y * b.y + __expf(b.z)) - b.w);
}

__global__ __launch_bounds__(256) void expr_kernel(
    const float4* __restrict__ in,   // N_ROWS*2 float4
    float* __restrict__ out,         // N_ROWS floats
    int n_rows)
{
    const int tid = threadIdx.x;
    const int base = blockIdx.x * 1024 + tid;   // 1024 rows per block

    const int r0 = base;
    const int r1 = base + 256;
    const int r2 = base + 512;
    const int r3 = base + 768;

    if (__builtin_expect(r3 < n_rows, 1)) {
        // Hot path (all CTAs when n_rows % 1024 == 0): 8 front-batched loads.
        float4 a0 = __ldcs(in + 2 * r0);
        float4 b0 = __ldcs(in + 2 * r0 + 1);
        float4 a1 = __ldcs(in + 2 * r1);
        float4 b1 = __ldcs(in + 2 * r1 + 1);
        float4 a2 = __ldcs(in + 2 * r2);
        float4 b2 = __ldcs(in + 2 * r2 + 1);
        float4 a3 = __ldcs(in + 2 * r3);
        float4 b3 = __ldcs(in + 2 * r3 + 1);

        __stcs(out + r0, expr1(a0, b0));
        __stcs(out + r1, expr1(a1, b1));
        __stcs(out + r2, expr1(a2, b2));
        __stcs(out + r3, expr1(a3, b3));
    } else {
        // Generic tail (unused at N_ROWS = 8388608).
        #pragma unroll
        for (int k = 0; k < 4; k++) {
            int r = base + k * 256;
            if (r < n_rows) {
                float4 a = __ldcs(in + 2 * r);
                float4 b = __ldcs(in + 2 * r + 1);
                __stcs(out + r, expr1(a, b));
            }
        }
    }
}

extern "C" void kernel_launch(void* const* d_in, const int* in_sizes, int n_in,
                              void* d_out, int out_size)
{
    const float4* in = (const float4*)d_in[0];
    float* out = (float*)d_out;

    int n_rows = out_size;   // 8388608
    int threads = 256;
    int rows_per_block = threads * 4;
    int blocks = (n_rows + rows_per_block - 1) / rows_per_block;  // 8192
    expr_kernel<<<blocks, threads>>>(in, out, n_rows);
}

// round 15
// speedup vs baseline: 1.0569x; 1.0232x over previous
#include <cuda_runtime.h>
#include <cuda_bf16.h>
#include <cstdint>

// out[r] = tanh((x0*x1 + sin(x2))*exp(-|x3|) + x4/(x5^2+exp(x6)) - x7)
// FINAL: flat grid, block=256, 4 rows/thread, warp-contiguous mapping
// (row = base + tid + k*256 => 32B lane stride), 8 front-batched LDG.128.CS
// (MLP=8), coalesced STG.32.CS.
// DRAM-streaming-bound at 82-85% of HBM spec (6.5-6.7 TB/s) — measured
// roofline across MLP{2,4,8,16}, persistent-vs-flat, and block-size sweeps.
// Five ncu profiles of this identical source span 42.8-45.4us purely from
// DVFS clock variance; bench scatter 43.7-48.2us. The a/b companion loads
// cover each other's 16B line gaps, so the 32B lane stride adds L1 wavefronts
// (35%, slack) but zero extra DRAM traffic — 1x-coalescing variants model to
// zero gain. Traffic (288MB) is irreducible; this is the roofline kernel.

__device__ __forceinline__ float expr1(float4 a, float4 b)
{
    return tanhf((a.x * a.y + __sinf(a.z)) * __expf(-fabsf(a.w))
               + __fdividef(b.x, b.y * b.y + __expf(b.z)) - b.w);
}

__global__ __launch_bounds__(256) void expr_kernel(
    const float4* __restrict__ in,   // N_ROWS*2 float4
    float* __restrict__ out,         // N_ROWS floats
    int n_rows)
{
    const int tid = threadIdx.x;
    const int base = blockIdx.x * 1024 + tid;   // 1024 rows per block

    const int r0 = base;
    const int r1 = base + 256;
    const int r2 = base + 512;
    const int r3 = base + 768;

    if (__builtin_expect(r3 < n_rows, 1)) {
        // Hot path (all CTAs when n_rows % 1024 == 0): 8 front-batched loads.
        float4 a0 = __ldcs(in + 2 * r0);
        float4 b0 = __ldcs(in + 2 * r0 + 1);
        float4 a1 = __ldcs(in + 2 * r1);
        float4 b1 = __ldcs(in + 2 * r1 + 1);
        float4 a2 = __ldcs(in + 2 * r2);
        float4 b2 = __ldcs(in + 2 * r2 + 1);
        float4 a3 = __ldcs(in + 2 * r3);
        float4 b3 = __ldcs(in + 2 * r3 + 1);

        __stcs(out + r0, expr1(a0, b0));
        __stcs(out + r1, expr1(a1, b1));
        __stcs(out + r2, expr1(a2, b2));
        __stcs(out + r3, expr1(a3, b3));
    } else {
        // Generic tail (unused at N_ROWS = 8388608).
        #pragma unroll
        for (int k = 0; k < 4; k++) {
            int r = base + k * 256;
            if (r < n_rows) {
                float4 a = __ldcs(in + 2 * r);
                float4 b = __ldcs(in + 2 * r + 1);
                __stcs(out + r, expr1(a, b));
            }
        }
    }
}

extern "C" void kernel_launch(void* const* d_in, const int* in_sizes, int n_in,
                              void* d_out, int out_size)
{
    const float4* in = (const float4*)d_in[0];
    float* out = (float*)d_out;

    int n_rows = out_size;   // 8388608
    int threads = 256;
    int rows_per_block = threads * 4;
    int blocks = (n_rows + rows_per_block - 1) / rows_per_block;  // 8192
    expr_kernel<<<blocks, threads>>>(in, out, n_rows);
}